// round 12
// baseline (speedup 1.0000x reference)
#include <cuda_runtime.h>
#include <cstdint>

#define ROWS   4096
#define FDIM   16384
#define BINS   128
#define NFEAT  257
#define OUT    64
#define HB     512
#define NW     (HB / 32)      // 16 warps
#define NCOPY  16             // per-warp histogram copies

// Written by wave-1 CTAs before their pass-1; read by all epilogues (much later)
__device__ __align__(16) float g_WTc[BINS * OUT];   // counts-part W, transposed [i][j]
__device__ __align__(16) float g_u[OUT];            // sum_k W[j][128+k]
__device__ __align__(16) float g_v[OUT];            // sum_k (k/128) W[j][128+k]

// ---------------------------------------------------------------------------
// Single fused kernel, no smem staging of x:
//   pass 1: coalesced LDG sweep -> row min/max (DRAM read, warms L2/L1)
//   pass 2: identical LDG sweep -> bin + shared atomic (L1/L2 hits)
//   epilogue: counts dot WTc + linear boundary fold
// ---------------------------------------------------------------------------
__global__ __launch_bounds__(HB, 4) void fused_kernel(const float* __restrict__ x,
                                                      const float* __restrict__ W,
                                                      const float* __restrict__ bias,
                                                      float* __restrict__ out) {
    __shared__ unsigned int hist[NCOPY * BINS];     // 8 KB
    __shared__ float  s_red[2 * NW];
    __shared__ float  s_mnw[2];
    __shared__ float  s_cnt[BINS];
    __shared__ float4 spart[NW * 16];               // 4 KB

    const int row  = blockIdx.x;
    const int tid  = threadIdx.x;
    const int warp = tid >> 5;
    const int lane = tid & 31;

    // zero per-warp histogram copies
    #pragma unroll
    for (int k = 0; k < (NCOPY * BINS) / HB; k++)
        hist[tid + k * HB] = 0u;

    // ---- one-time W prep (wave-1 CTAs; epilogue readers run much later) ----
    if (row < OUT) {
        if (tid < BINS) g_WTc[tid * OUT + row] = W[row * NFEAT + tid];
        if (tid == 0) __threadfence();
    } else if (row < 2 * OUT) {
        const int j = row - OUT;
        if (warp == 0) {
            const float* wb = W + j * NFEAT + BINS;      // W[j][128..256]
            float u = 0.0f, v = 0.0f;
            #pragma unroll
            for (int q = 0; q < 4; q++) {
                int k = q * 32 + lane;                   // 0..127
                float w = wb[k];
                u += w;
                v += (float)k * (1.0f / 128.0f) * w;
            }
            if (lane == 0) { u += wb[128]; v += wb[128]; }   // k=128 term, t=1
            #pragma unroll
            for (int o = 16; o > 0; o >>= 1) {
                u += __shfl_xor_sync(0xffffffffu, u, o);
                v += __shfl_xor_sync(0xffffffffu, v, o);
            }
            if (lane == 0) {
                g_u[j] = u;
                g_v[j] = v;
                __threadfence();
            }
        }
    }

    const float4* xr = reinterpret_cast<const float4*>(x) + (size_t)row * (FDIM / 4);

    // ---- pass 1: min/max over 8 x float4 per thread (DRAM read) ----
    float mn, mx;
    {
        float4 v0 = xr[tid];
        mn = fminf(fminf(v0.x, v0.y), fminf(v0.z, v0.w));
        mx = fmaxf(fmaxf(v0.x, v0.y), fmaxf(v0.z, v0.w));
        #pragma unroll
        for (int k = 1; k < 8; k++) {
            float4 v = xr[tid + k * HB];
            mn = fminf(mn, fminf(fminf(v.x, v.y), fminf(v.z, v.w)));
            mx = fmaxf(mx, fmaxf(fmaxf(v.x, v.y), fmaxf(v.z, v.w)));
        }
    }
    #pragma unroll
    for (int o = 16; o > 0; o >>= 1) {
        mn = fminf(mn, __shfl_xor_sync(0xffffffffu, mn, o));
        mx = fmaxf(mx, __shfl_xor_sync(0xffffffffu, mx, o));
    }
    if (lane == 0) { s_red[warp] = mn; s_red[NW + warp] = mx; }
    __syncthreads();
    if (tid == 0) {
        float m = s_red[0], M = s_red[NW];
        #pragma unroll
        for (int i = 1; i < NW; i++) {
            m = fminf(m, s_red[i]);
            M = fmaxf(M, s_red[NW + i]);
        }
        s_mnw[0] = m;
        s_mnw[1] = M - m;
    }
    __syncthreads();

    const float row_mn = s_mnw[0];
    const float width  = s_mnw[1];
    const float invw   = 128.0f / ((width == 0.0f) ? 1.0f : width);
    const float nmn    = -row_mn * invw;

    // ---- pass 2: re-read (L1/L2 hits), bin into this warp's private copy ----
    // v >= mn => fma >= -1ulp, so int-trunc == floor + lower clamp.
    unsigned int* h = &hist[warp * BINS];
    #pragma unroll
    for (int k = 0; k < 8; k++) {
        float4 v = xr[tid + k * HB];
        float vals[4] = {v.x, v.y, v.z, v.w};
        #pragma unroll
        for (int e = 0; e < 4; e++) {
            int b = (int)__fmaf_rn(vals[e], invw, nmn);
            b = min(b, BINS - 1);
            atomicAdd(&h[b], 1u);
        }
    }
    __syncthreads();

    // reduce the 16 copies
    if (tid < BINS) {
        unsigned int cnt = 0;
        #pragma unroll
        for (int c = 0; c < NCOPY; c++) cnt += hist[c * BINS + tid];
        s_cnt[tid] = (float)cnt;
    }
    __syncthreads();

    // ---- epilogue dot: thread = (j4 = tid&15, p = tid>>4); p covers 4 bins ----
    const int j4 = tid & 15;
    const int p  = tid >> 4;
    const float4* WTc4 = reinterpret_cast<const float4*>(g_WTc);

    float4 acc = make_float4(0.f, 0.f, 0.f, 0.f);
    #pragma unroll
    for (int k = 0; k < 4; k++) {
        int i = p * 4 + k;                            // 0..127
        float  fv = s_cnt[i];
        float4 wv = WTc4[i * (OUT / 4) + j4];
        acc.x += fv * wv.x;
        acc.y += fv * wv.y;
        acc.z += fv * wv.z;
        acc.w += fv * wv.w;
    }
    acc.x += __shfl_xor_sync(0xffffffffu, acc.x, 16);
    acc.y += __shfl_xor_sync(0xffffffffu, acc.y, 16);
    acc.z += __shfl_xor_sync(0xffffffffu, acc.z, 16);
    acc.w += __shfl_xor_sync(0xffffffffu, acc.w, 16);
    if (lane < 16) spart[warp * 16 + lane] = acc;
    __syncthreads();

    if (tid < OUT) {
        const float* sp = reinterpret_cast<const float*>(spart);  // [16][64]
        float s = 0.0f;
        #pragma unroll
        for (int w = 0; w < NW; w++) s += sp[w * OUT + tid];
        float o = s * (1.0f / 16384.0f)
                + row_mn * g_u[tid] + width * g_v[tid] + bias[tid];
        out[(size_t)row * OUT + tid] = o;
    }
}

// ---------------------------------------------------------------------------
extern "C" void kernel_launch(void* const* d_in, const int* in_sizes, int n_in,
                              void* d_out, int out_size) {
    const float* x    = (const float*)d_in[0];   // [4096, 16384]
    const float* W    = (const float*)d_in[1];   // [64, 257]
    const float* bias = (const float*)d_in[2];   // [64]
    float* out = (float*)d_out;                  // [4096, 64]

    fused_kernel<<<ROWS, HB>>>(x, W, bias, out);
}